// round 9
// baseline (speedup 1.0000x reference)
#include <cuda_runtime.h>
#include <cstdint>

#define BB   16
#define CC   32
#define HH   256
#define WW   256
#define T2   8
#define NT   16
#define NHC  32               // half-chunks (8 rows)
#define NQC  64               // quarter-chunks (4 rows each)
#define FIELD (HH*WW)
#define BT   (BB*T2)

typedef unsigned long long u64;

// ---------------- scratch (no cudaMalloc allowed) ----------------
__device__ __align__(256) float g_w1 [BT*FIELD];
__device__ __align__(256) float g_gv2[BT*FIELD];
__device__ __align__(256) float g_Sh [BT*3*NQC*WW];   // qc colsums (w3,w3p,w2p) -> suffix-excl after kS
__device__ __align__(256) float g_S3 [BT*NQC*WW];     // qc colsums of gv2 -> prefix-excl after kS2
__device__ u64 g_apk[T2*6*CC];                        // packed alphas

// ---------------- f32x2 helpers ----------------
__device__ __forceinline__ u64 fma2(u64 a, u64 b, u64 c) {
    u64 d; asm("fma.rn.f32x2 %0, %1, %2, %3;" : "=l"(d) : "l"(a), "l"(b), "l"(c)); return d;
}
__device__ __forceinline__ u64 add2(u64 a, u64 b) {
    u64 d; asm("add.rn.f32x2 %0, %1, %2;" : "=l"(d) : "l"(a), "l"(b)); return d;
}
__device__ __forceinline__ u64 pack2(float lo, float hi) {
    u64 r; asm("mov.b64 %0, {%1, %2};" : "=l"(r) : "f"(lo), "f"(hi)); return r;
}
__device__ __forceinline__ float2 unpack2(u64 v) {
    float2 f; asm("mov.b64 {%0, %1}, %2;" : "=f"(f.x), "=f"(f.y) : "l"(v)); return f;
}
__device__ __forceinline__ void LD8(float* v, const float* p) {
    float4 a = *(const float4*)p, b = *(const float4*)(p + 4);
    v[0]=a.x; v[1]=a.y; v[2]=a.z; v[3]=a.w; v[4]=b.x; v[5]=b.y; v[6]=b.z; v[7]=b.w;
}
__device__ __forceinline__ void ST8(float* p, const float* v) {
    *(float4*)p       = make_float4(v[0],v[1],v[2],v[3]);
    *(float4*)(p + 4) = make_float4(v[4],v[5],v[6],v[7]);
}
// unpack 4 u64 accs -> 8 floats
__device__ __forceinline__ void UNP8(float* v, const u64* q) {
    #pragma unroll
    for (int j = 0; j < 4; j++) {
        float2 u = unpack2(q[j]); v[2*j] = u.x; v[2*j+1] = u.y;
    }
}

// ---------------- warp scan: 256 elems, 8 per lane (warp-local) ----------------
__device__ __forceinline__ float wscan8(const float* v, float* incl) {
    float r = 0.f; float tmp[8];
    #pragma unroll
    for (int i = 0; i < 8; i++) { r += v[i]; tmp[i] = r; }
    float s = r;
    const int lane = threadIdx.x & 31;
    #pragma unroll
    for (int d = 1; d < 32; d <<= 1) {
        float n = __shfl_up_sync(0xffffffffu, s, d);
        if (lane >= d) s += n;
    }
    float excl = s - r;
    #pragma unroll
    for (int i = 0; i < 8; i++) incl[i] = tmp[i] + excl;
    return __shfl_sync(0xffffffffu, s, 31);
}

// =====================================================================
// K0: pack alphas duplicated into f32x2 pairs
// field order: 0=a1 1=a2 2=a3 3=a1p 4=a2p 5=a3p
// =====================================================================
__global__ void k0_pack(const float* __restrict__ a1,  const float* __restrict__ a2,
                        const float* __restrict__ a3,  const float* __restrict__ a1p,
                        const float* __restrict__ a2p, const float* __restrict__ a3p)
{
    int i = blockIdx.x * 256 + threadIdx.x;          // T2*6*CC = 1536
    if (i >= T2 * 6 * CC) return;
    int c = i % CC, f = (i / CC) % 6, t = i / (6 * CC);
    const float* p = (f == 0) ? a1 : (f == 1) ? a2 : (f == 2) ? a3
                   : (f == 3) ? a1p : (f == 4) ? a2p : a3p;
    float v = p[t * CC + c];
    g_apk[(t * 6 + f) * CC + c] = pack2(v, v);
}

// =====================================================================
// KAB: raw quarterchunk colsums contracted with alphas (all 8 trees).
// CTA = halfchunk: 2 rowgroups x 64 lanes x float4. rowgroup rg owns
// qc = hc*2+rg (no combine). grid = (NHC, BB) = 512 blocks.
// =====================================================================
__global__ void __launch_bounds__(128) kAB_colsum(const float* __restrict__ x)
{
    __shared__ __align__(16) u64 s_alB[CC][24];   // slot = k*8 + t
    const int tid = threadIdx.x;
    const int rg  = tid >> 6;
    const int l   = tid & 63;
    const int hc  = blockIdx.x;
    const int b   = blockIdx.y;
    const int qc  = hc * 2 + rg;
    const int col = l * 4;

    for (int i = tid; i < CC * 24; i += 128) {
        int slot = i % 24, c = i / 24;
        int k = slot / 8, t = slot % 8;
        int f = (k == 0) ? 2 : (k == 1) ? 5 : 4;   // a3, a3p, a2p
        s_alB[c][slot] = g_apk[(t * 6 + f) * CC + c];
    }
    __syncthreads();

    u64 acc[24][2];
    #pragma unroll
    for (int s = 0; s < 24; s++) { acc[s][0] = 0ull; acc[s][1] = 0ull; }

    #pragma unroll 2
    for (int c = 0; c < CC; c++) {
        const float4* xp = (const float4*)(x
            + ((size_t)(b * CC + c) * HH + qc * 4) * WW + col);
        u64 s01 = 0ull, s23 = 0ull;
        #pragma unroll
        for (int r = 0; r < 4; r++) {
            float4 v = xp[r * (WW / 4)];
            s01 = add2(s01, pack2(v.x, v.y));
            s23 = add2(s23, pack2(v.z, v.w));
        }
        #pragma unroll
        for (int j = 0; j < 12; j++) {
            ulonglong2 p = *(const ulonglong2*)&s_alB[c][2 * j];
            acc[2*j][0]   = fma2(s01, p.x, acc[2*j][0]);
            acc[2*j][1]   = fma2(s23, p.x, acc[2*j][1]);
            acc[2*j+1][0] = fma2(s01, p.y, acc[2*j+1][0]);
            acc[2*j+1][1] = fma2(s23, p.y, acc[2*j+1][1]);
        }
    }

    #pragma unroll
    for (int k = 0; k < 3; k++)
        #pragma unroll
        for (int t = 0; t < T2; t++) {
            int s = k * 8 + t;
            float2 v0 = unpack2(acc[s][0]), v1 = unpack2(acc[s][1]);
            size_t o = (((size_t)(b * T2 + t) * 3 + k) * NQC + qc) * WW + col;
            *(float4*)&g_Sh[o] = make_float4(v0.x, v0.y, v1.x, v1.y);
        }
}

// =====================================================================
// KS: in-place exclusive SUFFIX sum of g_Sh along qc (per bt,k,w column)
// =====================================================================
__global__ void kS_suffix()
{
    int gid = blockIdx.x * 128 + threadIdx.x;   // BT*3*WW = 98304
    int w   = gid & (WW - 1);
    int ktb = gid >> 8;
    float* base = g_Sh + (size_t)ktb * NQC * WW + w;
    float v[NQC];
    #pragma unroll
    for (int j = 0; j < NQC; j++) v[j] = base[(size_t)j * WW];
    float s = 0.f;
    #pragma unroll
    for (int j = NQC - 1; j >= 0; j--) {
        base[(size_t)j * WW] = s;
        s += v[j];
    }
}

// =====================================================================
// KS2: in-place exclusive PREFIX sum of g_S3 along qc
// =====================================================================
__global__ void kS2_prefix()
{
    int gid = blockIdx.x * 128 + threadIdx.x;   // BT*WW = 32768
    int w   = gid & (WW - 1);
    int bt  = gid >> 8;
    float* base = g_S3 + (size_t)bt * NQC * WW + w;
    float v[NQC];
    #pragma unroll
    for (int j = 0; j < NQC; j++) v[j] = base[(size_t)j * WW];
    float s = 0.f;
    #pragma unroll
    for (int j = 0; j < NQC; j++) {
        base[(size_t)j * WW] = s;
        s += v[j];
    }
}

// =====================================================================
// K1_FUSED v2: GEMM + bottom-up, WARP-LOCAL (no scan barriers).
// Warp = (tree-pair, quarterchunk), 32 lanes x 8 cols (full row width).
// CTA = 4 warps = 4 consecutive qcs. grid = (T2/2, NQC/4, BB) = 1024.
// Per channel per warp: 2 LDG.128 + 6 broadcast LDS.128 + 48 FFMA2.
// Emits: cherry -> out, gv2, w1, S3 (raw qc colsums of gv2).
// =====================================================================
__global__ void __launch_bounds__(128, 2) k1_fused(const float* __restrict__ x,
                                                   float* __restrict__ out)
{
    __shared__ __align__(16) u64 s_al[2][CC][6];

    const int wid  = threadIdx.x >> 5;
    const int lane = threadIdx.x & 31;
    const int col  = lane * 8;
    const int t0   = blockIdx.x * 2;
    const int c4   = blockIdx.y;
    const int b    = blockIdx.z;
    const int bt0  = b * T2 + t0;
    const int qc   = c4 * 4 + wid;

    for (int i = threadIdx.x; i < 2 * 6 * CC; i += 128) {
        int f = i % 6, c = (i / 6) % CC, tr = i / (6 * CC);
        s_al[tr][c][f] = g_apk[((t0 + tr) * 6 + f) * CC + c];
    }
    __syncthreads();

    // ---- init states from suffix-excl Sh (fwd/rev excl scans along w) ----
    float a3[2][8], p3[2][8], p2[2][8], cs[2][8], incl[8];
    #pragma unroll
    for (int tr = 0; tr < 2; tr++) {
        float v[8];
        const size_t sb = ((size_t)(bt0 + tr) * 3) * NQC * WW + (size_t)qc * WW + col;
        LD8(v, g_Sh + sb);
        wscan8(v, incl);
        #pragma unroll
        for (int i = 0; i < 8; i++) a3[tr][i] = incl[i] - v[i];
        LD8(v, g_Sh + sb + (size_t)NQC * WW);
        wscan8(v, incl);
        #pragma unroll
        for (int i = 0; i < 8; i++) p3[tr][i] = incl[i] - v[i];
        LD8(v, g_Sh + sb + 2 * (size_t)NQC * WW);
        float tot = wscan8(v, incl);
        #pragma unroll
        for (int i = 0; i < 8; i++) p2[tr][i] = tot - incl[i];
        #pragma unroll
        for (int i = 0; i < 8; i++) cs[tr][i] = 0.f;
    }

    // ---- 4 rows, bottom-up ----
    #pragma unroll 1
    for (int r = 3; r >= 0; r--) {
        const int h = qc * 4 + r;

        u64 acc[2][6][4];
        #pragma unroll
        for (int tr = 0; tr < 2; tr++)
            #pragma unroll
            for (int f = 0; f < 6; f++)
                #pragma unroll
                for (int j = 0; j < 4; j++) acc[tr][f][j] = 0ull;

        const float4* xq = (const float4*)(x + (size_t)b * CC * FIELD
                                             + (size_t)h * WW + col);
        // 2-deep channel prefetch (parity buffers)
        float4 p0[2], p1[2];
        p0[0] = xq[0];                 p1[0] = xq[1];
        p0[1] = xq[FIELD / 4];         p1[1] = xq[FIELD / 4 + 1];

        #pragma unroll 8
        for (int c = 0; c < CC; c++) {
            const int s = c & 1;
            u64 x01 = pack2(p0[s].x, p0[s].y);
            u64 x23 = pack2(p0[s].z, p0[s].w);
            u64 x45 = pack2(p1[s].x, p1[s].y);
            u64 x67 = pack2(p1[s].z, p1[s].w);
            if (c + 2 < CC) {
                p0[s] = xq[(size_t)(c + 2) * (FIELD / 4)];
                p1[s] = xq[(size_t)(c + 2) * (FIELD / 4) + 1];
            }
            #pragma unroll
            for (int tr = 0; tr < 2; tr++) {
                ulonglong2 pA = *(const ulonglong2*)&s_al[tr][c][0];
                ulonglong2 pB = *(const ulonglong2*)&s_al[tr][c][2];
                ulonglong2 pC = *(const ulonglong2*)&s_al[tr][c][4];
                acc[tr][0][0] = fma2(x01, pA.x, acc[tr][0][0]);
                acc[tr][0][1] = fma2(x23, pA.x, acc[tr][0][1]);
                acc[tr][0][2] = fma2(x45, pA.x, acc[tr][0][2]);
                acc[tr][0][3] = fma2(x67, pA.x, acc[tr][0][3]);
                acc[tr][1][0] = fma2(x01, pA.y, acc[tr][1][0]);
                acc[tr][1][1] = fma2(x23, pA.y, acc[tr][1][1]);
                acc[tr][1][2] = fma2(x45, pA.y, acc[tr][1][2]);
                acc[tr][1][3] = fma2(x67, pA.y, acc[tr][1][3]);
                acc[tr][2][0] = fma2(x01, pB.x, acc[tr][2][0]);
                acc[tr][2][1] = fma2(x23, pB.x, acc[tr][2][1]);
                acc[tr][2][2] = fma2(x45, pB.x, acc[tr][2][2]);
                acc[tr][2][3] = fma2(x67, pB.x, acc[tr][2][3]);
                acc[tr][3][0] = fma2(x01, pB.y, acc[tr][3][0]);
                acc[tr][3][1] = fma2(x23, pB.y, acc[tr][3][1]);
                acc[tr][3][2] = fma2(x45, pB.y, acc[tr][3][2]);
                acc[tr][3][3] = fma2(x67, pB.y, acc[tr][3][3]);
                acc[tr][4][0] = fma2(x01, pC.x, acc[tr][4][0]);
                acc[tr][4][1] = fma2(x23, pC.x, acc[tr][4][1]);
                acc[tr][4][2] = fma2(x45, pC.x, acc[tr][4][2]);
                acc[tr][4][3] = fma2(x67, pC.x, acc[tr][4][3]);
                acc[tr][5][0] = fma2(x01, pC.y, acc[tr][5][0]);
                acc[tr][5][1] = fma2(x23, pC.y, acc[tr][5][1]);
                acc[tr][5][2] = fma2(x45, pC.y, acc[tr][5][2]);
                acc[tr][5][3] = fma2(x67, pC.y, acc[tr][5][3]);
            }
        }

        #pragma unroll
        for (int tr = 0; tr < 2; tr++) {
            const size_t fb = (size_t)(bt0 + tr) * FIELD + (size_t)h * WW + col;
            float v[8];

            // gv2 = rev-excl-w-scan(w2 * a3); accumulate colsum
            UNP8(v, acc[tr][1]);
            #pragma unroll
            for (int i = 0; i < 8; i++) v[i] *= a3[tr][i];
            float tot = wscan8(v, incl);
            float gv[8];
            #pragma unroll
            for (int i = 0; i < 8; i++) { gv[i] = tot - incl[i]; cs[tr][i] += gv[i]; }
            ST8(g_gv2 + fb, gv);

            // w1
            UNP8(v, acc[tr][0]);
            ST8(g_w1 + fb, v);

            // cherry = w1p * p3 * p2 (strict-below states)
            UNP8(v, acc[tr][3]);
            #pragma unroll
            for (int i = 0; i < 8; i++) v[i] *= p3[tr][i] * p2[tr][i];
            ST8(out + ((size_t)(b * NT + T2 + t0 + tr)) * FIELD
                    + (size_t)h * WW + col, v);

            // state updates
            UNP8(v, acc[tr][2]);                    // w3
            wscan8(v, incl);
            #pragma unroll
            for (int i = 0; i < 8; i++) a3[tr][i] += incl[i] - v[i];

            UNP8(v, acc[tr][5]);                    // w3p
            wscan8(v, incl);
            #pragma unroll
            for (int i = 0; i < 8; i++) p3[tr][i] += incl[i] - v[i];

            UNP8(v, acc[tr][4]);                    // w2p
            tot = wscan8(v, incl);
            #pragma unroll
            for (int i = 0; i < 8; i++) p2[tr][i] += tot - incl[i];
        }
    }

    #pragma unroll
    for (int tr = 0; tr < 2; tr++)
        ST8(g_S3 + ((size_t)(bt0 + tr) * NQC + qc) * WW + col, cs[tr]);
}

// =====================================================================
// KD: top-down. linear = w1 * strict-north colsum of gv2.
// One warp per (qc,t,b) = 8192 warps; init from prefix-excl S3.
// =====================================================================
__global__ void __launch_bounds__(128) kD_topdown(float* __restrict__ out)
{
    const int wid  = threadIdx.x >> 5;
    const int lane = threadIdx.x & 31;
    const int gw   = blockIdx.x * 4 + wid;
    const int qc   =  gw        & 63;
    const int t    = (gw >> 6)  & 7;
    const int b    =  gw >> 9;
    const int bt   = b * T2 + t;
    const int col  = lane * 8;

    float va[8];
    LD8(va, g_S3 + ((size_t)bt * NQC + qc) * WW + col);   // prefix-excl

    const size_t fbase = (size_t)bt * FIELD + (size_t)(qc * 4) * WW + col;
    const size_t obase = ((size_t)(b * NT + t)) * FIELD + (size_t)(qc * 4) * WW + col;

    float w1b[8], gvb[8];
    LD8(w1b, g_w1 + fbase);
    LD8(gvb, g_gv2 + fbase);

    #pragma unroll
    for (int r = 0; r < 4; r++) {
        float w1n[8], gvn[8];
        if (r < 3) {
            LD8(w1n, g_w1  + fbase + (size_t)(r + 1) * WW);
            LD8(gvn, g_gv2 + fbase + (size_t)(r + 1) * WW);
        }
        float o[8];
        #pragma unroll
        for (int i = 0; i < 8; i++) o[i] = w1b[i] * va[i];
        ST8(out + obase + (size_t)r * WW, o);
        #pragma unroll
        for (int i = 0; i < 8; i++) va[i] += gvb[i];
        if (r < 3) {
            #pragma unroll
            for (int i = 0; i < 8; i++) { w1b[i] = w1n[i]; gvb[i] = gvn[i]; }
        }
    }
}

// =====================================================================
extern "C" void kernel_launch(void* const* d_in, const int* in_sizes, int n_in,
                              void* d_out, int out_size)
{
    const float* x   = (const float*)d_in[0];
    const float* a1  = (const float*)d_in[1];
    const float* a2  = (const float*)d_in[2];
    const float* a3  = (const float*)d_in[3];
    const float* a1p = (const float*)d_in[4];
    const float* a2p = (const float*)d_in[5];
    const float* a3p = (const float*)d_in[6];
    float* out = (float*)d_out;

    k0_pack<<<6, 256>>>(a1, a2, a3, a1p, a2p, a3p);

    dim3 gAB(NHC, BB);                          // (32, 16)
    kAB_colsum<<<gAB, 128>>>(x);

    kS_suffix<<<BT * 3 * WW / 128, 128>>>();    // 768 blocks

    dim3 gC(T2 / 2, NQC / 4, BB);               // (4, 16, 16) = 1024 CTAs
    k1_fused<<<gC, 128>>>(x, out);

    kS2_prefix<<<BT * WW / 128, 128>>>();       // 256 blocks

    kD_topdown<<<BT * NQC / 4, 128>>>(out);     // 2048 blocks
}